// round 1
// baseline (speedup 1.0000x reference)
#include <cuda_runtime.h>
#include <math.h>

// Problem constants
#define B_ 4
#define S_ 2048
#define D_ 1024
#define H_ 16
#define HD_ 64

// Scratch (device globals — no allocations allowed)
__device__ float g_Q[B_*S_*D_];
__device__ float g_K[B_*S_*D_];
__device__ float g_V[B_*S_*D_];
__device__ float g_O[B_*S_*D_];

// ---------------------------------------------------------------------------
// NT GEMM: C[m,n] = sum_k A[m,k] * Bm[n,k]
// A: [M,K] row-major, Bm: [N,K] row-major, C: [M,N] row-major.
// Tiles: BM=BN=128, BK=8; 256 threads; 8x8 register tile per thread.
// ---------------------------------------------------------------------------
__global__ __launch_bounds__(256) void gemm_nt_kernel(
    const float* __restrict__ A, const float* __restrict__ Bm,
    float* __restrict__ C, int M, int N, int K)
{
    __shared__ float As[8][128];
    __shared__ float Bs[8][128];

    const int tid = threadIdx.x;
    const int tx  = tid & 15;       // 0..15
    const int ty  = tid >> 4;       // 0..15
    const int bm  = blockIdx.y * 128;
    const int bn  = blockIdx.x * 128;

    // Loader mapping: each thread loads one float4 of A and one of Bm per k-tile.
    const int lrow = tid >> 1;          // 0..127
    const int lcol = (tid & 1) * 4;     // 0 or 4

    const float* Ap = A  + (size_t)(bm + lrow) * K + lcol;
    const float* Bp = Bm + (size_t)(bn + lrow) * K + lcol;

    float acc[8][8];
#pragma unroll
    for (int i = 0; i < 8; i++)
#pragma unroll
        for (int j = 0; j < 8; j++) acc[i][j] = 0.0f;

    for (int k0 = 0; k0 < K; k0 += 8) {
        float4 a4 = *(const float4*)(Ap + k0);
        float4 b4 = *(const float4*)(Bp + k0);
        As[lcol + 0][lrow] = a4.x;
        As[lcol + 1][lrow] = a4.y;
        As[lcol + 2][lrow] = a4.z;
        As[lcol + 3][lrow] = a4.w;
        Bs[lcol + 0][lrow] = b4.x;
        Bs[lcol + 1][lrow] = b4.y;
        Bs[lcol + 2][lrow] = b4.z;
        Bs[lcol + 3][lrow] = b4.w;
        __syncthreads();

#pragma unroll
        for (int k = 0; k < 8; k++) {
            float a[8], b[8];
#pragma unroll
            for (int i = 0; i < 8; i++) a[i] = As[k][ty * 8 + i];
#pragma unroll
            for (int j = 0; j < 8; j++) b[j] = Bs[k][tx * 8 + j];
#pragma unroll
            for (int i = 0; i < 8; i++)
#pragma unroll
                for (int j = 0; j < 8; j++)
                    acc[i][j] += a[i] * b[j];
        }
        __syncthreads();
    }

#pragma unroll
    for (int i = 0; i < 8; i++) {
        float* crow = C + (size_t)(bm + ty * 8 + i) * N + bn + tx * 8;
#pragma unroll
        for (int j = 0; j < 8; j++) crow[j] = acc[i][j];
    }
}

// ---------------------------------------------------------------------------
// RoPE applied in place to Q and K (layout [b, s, h, hd]).
// One thread per (pair) = (b,s,h,i) with dims 2i, 2i+1.
// ---------------------------------------------------------------------------
__global__ void rope_kernel(float* __restrict__ Q, float* __restrict__ K,
                            const int* __restrict__ pos)
{
    const int total = B_ * S_ * D_ / 2;
    int idx = blockIdx.x * blockDim.x + threadIdx.x;
    if (idx >= total) return;

    const int i    = idx & (HD_ / 2 - 1);        // 0..31, pair index in head
    const int rest = idx >> 5;
    const int bs   = rest >> 4;                  // b*S + s  (rest / H_)
    const int p    = pos[bs];

    // High-precision angle, range-reduced, then fp32 sincos.
    double inv = pow(10000.0, -((double)(2 * i)) / (double)HD_);
    double ang = (double)p * inv;
    const double TWO_PI = 6.283185307179586476925286766559;
    ang -= floor(ang / TWO_PI) * TWO_PI;
    float c, s;
    sincosf((float)ang, &s, &c);

    const size_t base = (size_t)idx * 2;   // contiguous: (bs*D + h*HD + 2i)
    float q1 = Q[base], q2 = Q[base + 1];
    Q[base]     = q1 * c - q2 * s;
    Q[base + 1] = q1 * s + q2 * c;
    float k1 = K[base], k2 = K[base + 1];
    K[base]     = k1 * c - k2 * s;
    K[base + 1] = k1 * s + k2 * c;
}

// ---------------------------------------------------------------------------
// Flash attention, fp32, causal. Q/K/V layout [b, s, h, hd].
// CTA: 64 queries x (loop over 64-wide KV tiles). 256 threads (16x16),
// each thread owns a 4x4 patch of the 64x64 score tile and a 4x4 patch
// of the 64x64 output accumulator.
// Dynamic smem: Qs[64][64], Ks[64][65] (reused for P), Vs[64][64].
// ---------------------------------------------------------------------------
__global__ __launch_bounds__(256) void attn_kernel(
    const float* __restrict__ Q, const float* __restrict__ K,
    const float* __restrict__ V, float* __restrict__ O)
{
    extern __shared__ float sm[];
    float* Qs = sm;                    // 64*64
    float* Ks = Qs + 64 * 64;          // 64*65 (padded), also holds P
    float* Vs = Ks + 64 * 65;          // 64*64

    const int tid = threadIdx.x;
    const int tx  = tid & 15;
    const int ty  = tid >> 4;
    const int bh  = blockIdx.y;
    const int b   = bh >> 4;           // / H_
    const int h   = bh & 15;           // % H_
    const int q0  = blockIdx.x * 64;

    const size_t boff = (size_t)b * S_ * D_ + (size_t)h * HD_;
    const float scale = 0.125f;        // 1/sqrt(64)

    // Load Q tile (scaled). 1024 float4s, 4 per thread.
    for (int t = tid; t < 64 * 16; t += 256) {
        int r = t >> 4;
        int c = (t & 15) << 2;
        float4 v = *(const float4*)(Q + boff + (size_t)(q0 + r) * D_ + c);
        Qs[r * 64 + c + 0] = v.x * scale;
        Qs[r * 64 + c + 1] = v.y * scale;
        Qs[r * 64 + c + 2] = v.z * scale;
        Qs[r * 64 + c + 3] = v.w * scale;
    }

    float m_i[4], l_i[4], acc[4][4];
#pragma unroll
    for (int i = 0; i < 4; i++) {
        m_i[i] = -INFINITY;
        l_i[i] = 0.0f;
#pragma unroll
        for (int j = 0; j < 4; j++) acc[i][j] = 0.0f;
    }

    for (int k0 = 0; k0 <= q0; k0 += 64) {
        __syncthreads();   // previous AV done with Ks/Vs
        // Load K and V tiles.
        for (int t = tid; t < 64 * 16; t += 256) {
            int r = t >> 4;
            int c = (t & 15) << 2;
            float4 kv = *(const float4*)(K + boff + (size_t)(k0 + r) * D_ + c);
            Ks[r * 65 + c + 0] = kv.x;
            Ks[r * 65 + c + 1] = kv.y;
            Ks[r * 65 + c + 2] = kv.z;
            Ks[r * 65 + c + 3] = kv.w;
            float4 vv = *(const float4*)(V + boff + (size_t)(k0 + r) * D_ + c);
            Vs[r * 64 + c + 0] = vv.x;
            Vs[r * 64 + c + 1] = vv.y;
            Vs[r * 64 + c + 2] = vv.z;
            Vs[r * 64 + c + 3] = vv.w;
        }
        __syncthreads();

        // Scores: sc[i][j] = Qrow(ty*4+i) . Krow(tx*4+j)
        float sc[4][4];
#pragma unroll
        for (int i = 0; i < 4; i++)
#pragma unroll
            for (int j = 0; j < 4; j++) sc[i][j] = 0.0f;

#pragma unroll 8
        for (int k = 0; k < 64; k++) {
            float qv[4], kv[4];
#pragma unroll
            for (int i = 0; i < 4; i++) qv[i] = Qs[(ty * 4 + i) * 64 + k];
#pragma unroll
            for (int j = 0; j < 4; j++) kv[j] = Ks[(tx * 4 + j) * 65 + k];
#pragma unroll
            for (int i = 0; i < 4; i++)
#pragma unroll
                for (int j = 0; j < 4; j++)
                    sc[i][j] += qv[i] * kv[j];
        }

        // Causal mask + online softmax update. Row stats replicated across
        // the 16 lanes (same ty) via width-16 shuffles.
        float p[4][4];
#pragma unroll
        for (int i = 0; i < 4; i++) {
            int qg = q0 + ty * 4 + i;
            float mloc = -INFINITY;
#pragma unroll
            for (int j = 0; j < 4; j++) {
                int kg = k0 + tx * 4 + j;
                if (kg > qg) sc[i][j] = -INFINITY;
                mloc = fmaxf(mloc, sc[i][j]);
            }
#pragma unroll
            for (int off = 8; off > 0; off >>= 1)
                mloc = fmaxf(mloc, __shfl_xor_sync(0xffffffffu, mloc, off, 16));
            float mnew = fmaxf(m_i[i], mloc);
            float corr = expf(m_i[i] - mnew);
            float lsum = 0.0f;
#pragma unroll
            for (int j = 0; j < 4; j++) {
                p[i][j] = expf(sc[i][j] - mnew);
                lsum += p[i][j];
            }
#pragma unroll
            for (int off = 8; off > 0; off >>= 1)
                lsum += __shfl_xor_sync(0xffffffffu, lsum, off, 16);
            l_i[i] = l_i[i] * corr + lsum;
#pragma unroll
            for (int j = 0; j < 4; j++) acc[i][j] *= corr;
            m_i[i] = mnew;
        }

        __syncthreads();   // all done reading Ks as K
        // Write P into Ks buffer.
#pragma unroll
        for (int i = 0; i < 4; i++)
#pragma unroll
            for (int j = 0; j < 4; j++)
                Ks[(ty * 4 + i) * 65 + tx * 4 + j] = p[i][j];
        __syncthreads();

        // acc += P * V
#pragma unroll 8
        for (int k = 0; k < 64; k++) {
            float pv[4], vv[4];
#pragma unroll
            for (int i = 0; i < 4; i++) pv[i] = Ks[(ty * 4 + i) * 65 + k];
#pragma unroll
            for (int j = 0; j < 4; j++) vv[j] = Vs[k * 64 + tx * 4 + j];
#pragma unroll
            for (int i = 0; i < 4; i++)
#pragma unroll
                for (int j = 0; j < 4; j++)
                    acc[i][j] += pv[i] * vv[j];
        }
    }

    // Epilogue: O[b, q, h, hd] = acc / l
#pragma unroll
    for (int i = 0; i < 4; i++) {
        float invl = 1.0f / l_i[i];
        float* orow = O + boff + (size_t)(q0 + ty * 4 + i) * D_ + tx * 4;
#pragma unroll
        for (int j = 0; j < 4; j++) orow[j] = acc[i][j] * invl;
    }
}

// ---------------------------------------------------------------------------
// Launch
// ---------------------------------------------------------------------------
extern "C" void kernel_launch(void* const* d_in, const int* in_sizes, int n_in,
                              void* d_out, int out_size)
{
    (void)in_sizes; (void)n_in; (void)out_size;
    const float* x   = (const float*)d_in[0];
    const int*   pos = (const int*)  d_in[1];
    const float* Wq  = (const float*)d_in[2];
    const float* Wk  = (const float*)d_in[3];
    const float* Wv  = (const float*)d_in[4];
    const float* Wo  = (const float*)d_in[5];
    float* out = (float*)d_out;

    void *pQ, *pK, *pV, *pO;
    cudaGetSymbolAddress(&pQ, g_Q);
    cudaGetSymbolAddress(&pK, g_K);
    cudaGetSymbolAddress(&pV, g_V);
    cudaGetSymbolAddress(&pO, g_O);

    const int M = B_ * S_;   // 8192
    const int N = D_;        // 1024
    const int K = D_;        // 1024

    dim3 gblk(256);
    dim3 ggrid(N / 128, M / 128);   // (8, 64)

    gemm_nt_kernel<<<ggrid, gblk>>>(x, Wq, (float*)pQ, M, N, K);
    gemm_nt_kernel<<<ggrid, gblk>>>(x, Wk, (float*)pK, M, N, K);
    gemm_nt_kernel<<<ggrid, gblk>>>(x, Wv, (float*)pV, M, N, K);

    const int pairs = B_ * S_ * D_ / 2;
    rope_kernel<<<(pairs + 255) / 256, 256>>>((float*)pQ, (float*)pK, pos);

    const int attn_smem = (64 * 64 + 64 * 65 + 64 * 64) * (int)sizeof(float); // 49408
    cudaFuncSetAttribute(attn_kernel,
                         cudaFuncAttributeMaxDynamicSharedMemorySize, attn_smem);
    dim3 agrid(S_ / 64, B_ * H_);   // (32, 64)
    attn_kernel<<<agrid, 256, attn_smem>>>((const float*)pQ, (const float*)pK,
                                           (const float*)pV, (float*)pO);

    gemm_nt_kernel<<<ggrid, gblk>>>((const float*)pO, Wo, out, M, N, K);
}

// round 3
// speedup vs baseline: 1.6081x; 1.6081x over previous
#include <cuda_runtime.h>
#include <cuda_bf16.h>
#include <math.h>
#include <cstdint>

#define B_ 4
#define S_ 2048
#define D_ 1024
#define H_ 16
#define HD_ 64

// Scratch (device globals — no allocations allowed)
__device__ float g_Q[B_*S_*D_];
__device__ float g_K[B_*S_*D_];
__device__ float g_V[B_*S_*D_];
__device__ float g_O[B_*S_*D_];

// ---------------------------------------------------------------------------
// mma.sync helpers (baseline PTX ISA — works on plain sm_103 target)
// ---------------------------------------------------------------------------
__device__ __forceinline__ void mma_bf16(float& c0, float& c1, float& c2, float& c3,
                                         uint32_t a0, uint32_t a1, uint32_t a2, uint32_t a3,
                                         uint32_t b0, uint32_t b1)
{
    asm volatile(
        "mma.sync.aligned.m16n8k16.row.col.f32.bf16.bf16.f32 "
        "{%0,%1,%2,%3}, {%4,%5,%6,%7}, {%8,%9}, {%0,%1,%2,%3};"
        : "+f"(c0), "+f"(c1), "+f"(c2), "+f"(c3)
        : "r"(a0), "r"(a1), "r"(a2), "r"(a3), "r"(b0), "r"(b1));
}

__device__ __forceinline__ uint32_t pack_bf16(__nv_bfloat16 lo16, __nv_bfloat16 hi16) {
    uint32_t w = (uint32_t)__bfloat16_as_ushort(lo16)
               | ((uint32_t)__bfloat16_as_ushort(hi16) << 16);
    return w;
}

// Split x into bf16 hi + bf16 lo (residual).
__device__ __forceinline__ void split_bf16(float x, __nv_bfloat16& h, __nv_bfloat16& l) {
    h = __float2bfloat16_rn(x);
    l = __float2bfloat16_rn(x - __bfloat162float(h));
}

// Permuted column for packed word w (w = k/2, 0..15 per 32-wide chunk):
// col' = 2*(w&7) + (w>>3). Thread tig then reads both k16-steps as one LDS.64.
__device__ __forceinline__ int permcol(int w) { return 2 * (w & 7) + (w >> 3); }

// ---------------------------------------------------------------------------
// bf16x3 NT GEMM: C[m,n] = sum_k A[m,k] * W[n,k]  (fp32-accurate via hi/lo split)
// CTA 128x128, K-chunk 32. 8 warps (2x4), warp tile 64x32 (4x4 m16n8 tiles).
// Smem: Ah/Al/Wh/Wl packed bf16x2, 128 rows x 24 words (stride-24 anti-conflict).
// ---------------------------------------------------------------------------
#define GW_STRIDE 24
#define GW_TILE   (128 * GW_STRIDE)              // words per tile
#define G3_SMEM_BYTES (4 * GW_TILE * 4)          // 49152 B

__global__ __launch_bounds__(256) void gemm_bf16x3_kernel(
    const float* __restrict__ A, const float* __restrict__ W,
    float* __restrict__ C, int M, int N, int K)
{
    extern __shared__ __align__(16) uint32_t sm3[];
    uint32_t* Ah = sm3;
    uint32_t* Al = sm3 + GW_TILE;
    uint32_t* Wh = sm3 + 2 * GW_TILE;
    uint32_t* Wl = sm3 + 3 * GW_TILE;

    const int tid = threadIdx.x;
    const int wid = tid >> 5;
    const int lid = tid & 31;
    const int gid = lid >> 2;      // group of 4
    const int tig = lid & 3;       // thread in group
    const int row0 = (wid >> 2) * 64;
    const int col0 = (wid & 3) * 32;
    const int bm = blockIdx.y * 128;
    const int bn = blockIdx.x * 128;

    float acc[4][4][4];
#pragma unroll
    for (int mt = 0; mt < 4; mt++)
#pragma unroll
        for (int nt = 0; nt < 4; nt++)
#pragma unroll
            for (int e = 0; e < 4; e++) acc[mt][nt][e] = 0.0f;

    const int nchunk = K / 32;
    for (int ck = 0; ck < nchunk; ck++) {
        __syncthreads();   // previous chunk's fragment reads complete
#pragma unroll
        for (int j = 0; j < 4; j++) {
            int idx = tid + 256 * j;           // 0..1023
            int r   = idx >> 3;                // 0..127
            int c   = (idx & 7) << 2;          // 0..28
            float4 av = *(const float4*)(A + (size_t)(bm + r) * K + ck * 32 + c);
            float4 wv = *(const float4*)(W + (size_t)(bn + r) * K + ck * 32 + c);

            int w0 = c >> 1, w1 = w0 + 1;
            int c0p = permcol(w0), c1p = permcol(w1);

            __nv_bfloat16 h0,l0,h1,l1,h2,l2,h3,l3;
            split_bf16(av.x, h0, l0); split_bf16(av.y, h1, l1);
            split_bf16(av.z, h2, l2); split_bf16(av.w, h3, l3);
            Ah[r * GW_STRIDE + c0p] = pack_bf16(h0, h1);
            Ah[r * GW_STRIDE + c1p] = pack_bf16(h2, h3);
            Al[r * GW_STRIDE + c0p] = pack_bf16(l0, l1);
            Al[r * GW_STRIDE + c1p] = pack_bf16(l2, l3);

            split_bf16(wv.x, h0, l0); split_bf16(wv.y, h1, l1);
            split_bf16(wv.z, h2, l2); split_bf16(wv.w, h3, l3);
            Wh[r * GW_STRIDE + c0p] = pack_bf16(h0, h1);
            Wh[r * GW_STRIDE + c1p] = pack_bf16(h2, h3);
            Wl[r * GW_STRIDE + c0p] = pack_bf16(l0, l1);
            Wl[r * GW_STRIDE + c1p] = pack_bf16(l2, l3);
        }
        __syncthreads();

        // B fragments for all 4 n-tiles (both k16 steps: .x = kk0, .y = kk1)
        uint2 bh0[4], bh1[4], bl0[4], bl1[4];
#pragma unroll
        for (int nt = 0; nt < 4; nt++) {
            int n = col0 + nt * 8 + gid;
            const uint2* ph = (const uint2*)(Wh + n * GW_STRIDE);
            const uint2* pl = (const uint2*)(Wl + n * GW_STRIDE);
            bh0[nt] = ph[tig];     bh1[nt] = ph[tig + 4];
            bl0[nt] = pl[tig];     bl1[nt] = pl[tig + 4];
        }

#pragma unroll
        for (int mt = 0; mt < 4; mt++) {
            int r1 = row0 + mt * 16 + gid;
            const uint2* ph1 = (const uint2*)(Ah + r1 * GW_STRIDE);
            const uint2* ph2 = (const uint2*)(Ah + (r1 + 8) * GW_STRIDE);
            const uint2* pl1 = (const uint2*)(Al + r1 * GW_STRIDE);
            const uint2* pl2 = (const uint2*)(Al + (r1 + 8) * GW_STRIDE);
            uint2 ah0 = ph1[tig], ah2 = ph1[tig + 4];
            uint2 ah1 = ph2[tig], ah3 = ph2[tig + 4];
            uint2 al0 = pl1[tig], al2 = pl1[tig + 4];
            uint2 al1 = pl2[tig], al3 = pl2[tig + 4];

#pragma unroll
            for (int nt = 0; nt < 4; nt++) {
                float* c = acc[mt][nt];
                // k16 step 0
                mma_bf16(c[0],c[1],c[2],c[3], ah0.x,ah1.x,ah2.x,ah3.x, bh0[nt].x, bh1[nt].x);
                mma_bf16(c[0],c[1],c[2],c[3], al0.x,al1.x,al2.x,al3.x, bh0[nt].x, bh1[nt].x);
                mma_bf16(c[0],c[1],c[2],c[3], ah0.x,ah1.x,ah2.x,ah3.x, bl0[nt].x, bl1[nt].x);
                // k16 step 1
                mma_bf16(c[0],c[1],c[2],c[3], ah0.y,ah1.y,ah2.y,ah3.y, bh0[nt].y, bh1[nt].y);
                mma_bf16(c[0],c[1],c[2],c[3], al0.y,al1.y,al2.y,al3.y, bh0[nt].y, bh1[nt].y);
                mma_bf16(c[0],c[1],c[2],c[3], ah0.y,ah1.y,ah2.y,ah3.y, bl0[nt].y, bl1[nt].y);
            }
        }
    }

    // Epilogue
#pragma unroll
    for (int mt = 0; mt < 4; mt++) {
        int row = bm + row0 + mt * 16 + gid;
#pragma unroll
        for (int nt = 0; nt < 4; nt++) {
            int col = bn + col0 + nt * 8 + 2 * tig;
            float2 v0 = make_float2(acc[mt][nt][0], acc[mt][nt][1]);
            float2 v1 = make_float2(acc[mt][nt][2], acc[mt][nt][3]);
            *(float2*)(C + (size_t)row * N + col)       = v0;
            *(float2*)(C + (size_t)(row + 8) * N + col) = v1;
        }
    }
}

// ---------------------------------------------------------------------------
// RoPE (pure fp32, matching the fp32 reference math). In-place on Q and K.
// ---------------------------------------------------------------------------
__global__ void rope_kernel(float* __restrict__ Q, float* __restrict__ K,
                            const int* __restrict__ pos)
{
    const int total = B_ * S_ * D_ / 2;
    int idx = blockIdx.x * blockDim.x + threadIdx.x;
    if (idx >= total) return;

    const int i  = idx & (HD_ / 2 - 1);          // pair index in head (0..31)
    const int bs = idx >> 9;                     // / (D_/2)
    const int p  = pos[bs];

    float inv = exp2f(-(float)i * 0.41524101186092f);  // 10000^(-2i/64)
    float ang = (float)p * inv;
    float c, s;
    sincosf(ang, &s, &c);

    const size_t base = (size_t)idx * 2;
    float q1 = Q[base], q2 = Q[base + 1];
    Q[base]     = q1 * c - q2 * s;
    Q[base + 1] = q1 * s + q2 * c;
    float k1 = K[base], k2 = K[base + 1];
    K[base]     = k1 * c - k2 * s;
    K[base + 1] = k1 * s + k2 * c;
}

// ---------------------------------------------------------------------------
// Flash attention, fp32, causal (unchanged — R4 target).
// ---------------------------------------------------------------------------
__global__ __launch_bounds__(256) void attn_kernel(
    const float* __restrict__ Q, const float* __restrict__ K,
    const float* __restrict__ V, float* __restrict__ O)
{
    extern __shared__ float smf[];
    float* Qs = smf;                   // 64*64
    float* Ks = Qs + 64 * 64;          // 64*65 (padded), also holds P
    float* Vs = Ks + 64 * 65;          // 64*64

    const int tid = threadIdx.x;
    const int tx  = tid & 15;
    const int ty  = tid >> 4;
    const int bh  = blockIdx.y;
    const int b   = bh >> 4;
    const int h   = bh & 15;
    const int q0  = blockIdx.x * 64;

    const size_t boff = (size_t)b * S_ * D_ + (size_t)h * HD_;
    const float scale = 0.125f;

    for (int t = tid; t < 64 * 16; t += 256) {
        int r = t >> 4;
        int c = (t & 15) << 2;
        float4 v = *(const float4*)(Q + boff + (size_t)(q0 + r) * D_ + c);
        Qs[r * 64 + c + 0] = v.x * scale;
        Qs[r * 64 + c + 1] = v.y * scale;
        Qs[r * 64 + c + 2] = v.z * scale;
        Qs[r * 64 + c + 3] = v.w * scale;
    }

    float m_i[4], l_i[4], acc[4][4];
#pragma unroll
    for (int i = 0; i < 4; i++) {
        m_i[i] = -INFINITY;
        l_i[i] = 0.0f;
#pragma unroll
        for (int j = 0; j < 4; j++) acc[i][j] = 0.0f;
    }

    for (int k0 = 0; k0 <= q0; k0 += 64) {
        __syncthreads();
        for (int t = tid; t < 64 * 16; t += 256) {
            int r = t >> 4;
            int c = (t & 15) << 2;
            float4 kv = *(const float4*)(K + boff + (size_t)(k0 + r) * D_ + c);
            Ks[r * 65 + c + 0] = kv.x;
            Ks[r * 65 + c + 1] = kv.y;
            Ks[r * 65 + c + 2] = kv.z;
            Ks[r * 65 + c + 3] = kv.w;
            float4 vv = *(const float4*)(V + boff + (size_t)(k0 + r) * D_ + c);
            Vs[r * 64 + c + 0] = vv.x;
            Vs[r * 64 + c + 1] = vv.y;
            Vs[r * 64 + c + 2] = vv.z;
            Vs[r * 64 + c + 3] = vv.w;
        }
        __syncthreads();

        float sc[4][4];
#pragma unroll
        for (int i = 0; i < 4; i++)
#pragma unroll
            for (int j = 0; j < 4; j++) sc[i][j] = 0.0f;

#pragma unroll 8
        for (int k = 0; k < 64; k++) {
            float qv[4], kv[4];
#pragma unroll
            for (int i = 0; i < 4; i++) qv[i] = Qs[(ty * 4 + i) * 64 + k];
#pragma unroll
            for (int j = 0; j < 4; j++) kv[j] = Ks[(tx * 4 + j) * 65 + k];
#pragma unroll
            for (int i = 0; i < 4; i++)
#pragma unroll
                for (int j = 0; j < 4; j++)
                    sc[i][j] += qv[i] * kv[j];
        }

        float p[4][4];
#pragma unroll
        for (int i = 0; i < 4; i++) {
            int qg = q0 + ty * 4 + i;
            float mloc = -INFINITY;
#pragma unroll
            for (int j = 0; j < 4; j++) {
                int kg = k0 + tx * 4 + j;
                if (kg > qg) sc[i][j] = -INFINITY;
                mloc = fmaxf(mloc, sc[i][j]);
            }
#pragma unroll
            for (int off = 8; off > 0; off >>= 1)
                mloc = fmaxf(mloc, __shfl_xor_sync(0xffffffffu, mloc, off, 16));
            float mnew = fmaxf(m_i[i], mloc);
            float corr = expf(m_i[i] - mnew);
            float lsum = 0.0f;
#pragma unroll
            for (int j = 0; j < 4; j++) {
                p[i][j] = expf(sc[i][j] - mnew);
                lsum += p[i][j];
            }
#pragma unroll
            for (int off = 8; off > 0; off >>= 1)
                lsum += __shfl_xor_sync(0xffffffffu, lsum, off, 16);
            l_i[i] = l_i[i] * corr + lsum;
#pragma unroll
            for (int j = 0; j < 4; j++) acc[i][j] *= corr;
            m_i[i] = mnew;
        }

        __syncthreads();
#pragma unroll
        for (int i = 0; i < 4; i++)
#pragma unroll
            for (int j = 0; j < 4; j++)
                Ks[(ty * 4 + i) * 65 + tx * 4 + j] = p[i][j];
        __syncthreads();

#pragma unroll 8
        for (int k = 0; k < 64; k++) {
            float pv[4], vv[4];
#pragma unroll
            for (int i = 0; i < 4; i++) pv[i] = Ks[(ty * 4 + i) * 65 + k];
#pragma unroll
            for (int j = 0; j < 4; j++) vv[j] = Vs[k * 64 + tx * 4 + j];
#pragma unroll
            for (int i = 0; i < 4; i++)
#pragma unroll
                for (int j = 0; j < 4; j++)
                    acc[i][j] += pv[i] * vv[j];
        }
    }

#pragma unroll
    for (int i = 0; i < 4; i++) {
        float invl = 1.0f / l_i[i];
        float* orow = O + boff + (size_t)(q0 + ty * 4 + i) * D_ + tx * 4;
#pragma unroll
        for (int j = 0; j < 4; j++) orow[j] = acc[i][j] * invl;
    }
}

// ---------------------------------------------------------------------------
// Launch
// ---------------------------------------------------------------------------
extern "C" void kernel_launch(void* const* d_in, const int* in_sizes, int n_in,
                              void* d_out, int out_size)
{
    (void)in_sizes; (void)n_in; (void)out_size;
    const float* x   = (const float*)d_in[0];
    const int*   pos = (const int*)  d_in[1];
    const float* Wq  = (const float*)d_in[2];
    const float* Wk  = (const float*)d_in[3];
    const float* Wv  = (const float*)d_in[4];
    const float* Wo  = (const float*)d_in[5];
    float* out = (float*)d_out;

    void *pQ, *pK, *pV, *pO;
    cudaGetSymbolAddress(&pQ, g_Q);
    cudaGetSymbolAddress(&pK, g_K);
    cudaGetSymbolAddress(&pV, g_V);
    cudaGetSymbolAddress(&pO, g_O);

    const int M = B_ * S_;   // 8192
    const int N = D_;        // 1024
    const int K = D_;        // 1024

    cudaFuncSetAttribute(gemm_bf16x3_kernel,
                         cudaFuncAttributeMaxDynamicSharedMemorySize, G3_SMEM_BYTES);

    dim3 gblk(256);
    dim3 ggrid(N / 128, M / 128);   // (8, 64)

    gemm_bf16x3_kernel<<<ggrid, gblk, G3_SMEM_BYTES>>>(x, Wq, (float*)pQ, M, N, K);
    gemm_bf16x3_kernel<<<ggrid, gblk, G3_SMEM_BYTES>>>(x, Wk, (float*)pK, M, N, K);
    gemm_bf16x3_kernel<<<ggrid, gblk, G3_SMEM_BYTES>>>(x, Wv, (float*)pV, M, N, K);

    const int pairs = B_ * S_ * D_ / 2;
    rope_kernel<<<(pairs + 255) / 256, 256>>>((float*)pQ, (float*)pK, pos);

    const int attn_smem = (64 * 64 + 64 * 65 + 64 * 64) * (int)sizeof(float); // 49408
    cudaFuncSetAttribute(attn_kernel,
                         cudaFuncAttributeMaxDynamicSharedMemorySize, attn_smem);
    dim3 agrid(S_ / 64, B_ * H_);   // (32, 64)
    attn_kernel<<<agrid, 256, attn_smem>>>((const float*)pQ, (const float*)pK,
                                           (const float*)pV, (float*)pO);

    gemm_bf16x3_kernel<<<ggrid, gblk, G3_SMEM_BYTES>>>((const float*)pO, Wo, out, M, N, K);
}

// round 4
// speedup vs baseline: 2.1076x; 1.3106x over previous
#include <cuda_runtime.h>
#include <cuda_bf16.h>
#include <math.h>
#include <cstdint>

#define B_ 4
#define S_ 2048
#define D_ 1024
#define H_ 16
#define HD_ 64

// Scratch (device globals — no allocations allowed)
__device__ float g_Q[B_*S_*D_];
__device__ float g_K[B_*S_*D_];
__device__ float g_V[B_*S_*D_];
__device__ float g_O[B_*S_*D_];

// ---------------------------------------------------------------------------
// mma.sync helpers (baseline PTX ISA — works on plain sm_103 target)
// ---------------------------------------------------------------------------
__device__ __forceinline__ void mma_bf16(float& c0, float& c1, float& c2, float& c3,
                                         uint32_t a0, uint32_t a1, uint32_t a2, uint32_t a3,
                                         uint32_t b0, uint32_t b1)
{
    asm volatile(
        "mma.sync.aligned.m16n8k16.row.col.f32.bf16.bf16.f32 "
        "{%0,%1,%2,%3}, {%4,%5,%6,%7}, {%8,%9}, {%0,%1,%2,%3};"
        : "+f"(c0), "+f"(c1), "+f"(c2), "+f"(c3)
        : "r"(a0), "r"(a1), "r"(a2), "r"(a3), "r"(b0), "r"(b1));
}

__device__ __forceinline__ uint32_t pack_bf16(__nv_bfloat16 lo16, __nv_bfloat16 hi16) {
    return (uint32_t)__bfloat16_as_ushort(lo16)
         | ((uint32_t)__bfloat16_as_ushort(hi16) << 16);
}

__device__ __forceinline__ void split_bf16(float x, __nv_bfloat16& h, __nv_bfloat16& l) {
    h = __float2bfloat16_rn(x);
    l = __float2bfloat16_rn(x - __bfloat162float(h));
}

// Pack two fp32 into one bf16x2 word (hi parts) and one (lo parts).
__device__ __forceinline__ void split_pack2(float x0, float x1, uint32_t& wh, uint32_t& wl) {
    __nv_bfloat16 h0, l0, h1, l1;
    split_bf16(x0, h0, l0);
    split_bf16(x1, h1, l1);
    wh = pack_bf16(h0, h1);
    wl = pack_bf16(l0, l1);
}

// Storage column for logical packed-pair w (0..15): col' = 2*(w&7) + (w>>3).
__device__ __forceinline__ int permcol(int w) { return 2 * (w & 7) + (w >> 3); }

// ---------------------------------------------------------------------------
// bf16x3 NT GEMM (unchanged from R3 — passing at ~1e-5)
// ---------------------------------------------------------------------------
#define GW_STRIDE 24
#define GW_TILE   (128 * GW_STRIDE)
#define G3_SMEM_BYTES (4 * GW_TILE * 4)

__global__ __launch_bounds__(256) void gemm_bf16x3_kernel(
    const float* __restrict__ A, const float* __restrict__ W,
    float* __restrict__ C, int M, int N, int K)
{
    extern __shared__ __align__(16) uint32_t sm3[];
    uint32_t* Ah = sm3;
    uint32_t* Al = sm3 + GW_TILE;
    uint32_t* Wh = sm3 + 2 * GW_TILE;
    uint32_t* Wl = sm3 + 3 * GW_TILE;

    const int tid = threadIdx.x;
    const int wid = tid >> 5;
    const int lid = tid & 31;
    const int gid = lid >> 2;
    const int tig = lid & 3;
    const int row0 = (wid >> 2) * 64;
    const int col0 = (wid & 3) * 32;
    const int bm = blockIdx.y * 128;
    const int bn = blockIdx.x * 128;

    float acc[4][4][4];
#pragma unroll
    for (int mt = 0; mt < 4; mt++)
#pragma unroll
        for (int nt = 0; nt < 4; nt++)
#pragma unroll
            for (int e = 0; e < 4; e++) acc[mt][nt][e] = 0.0f;

    const int nchunk = K / 32;
    for (int ck = 0; ck < nchunk; ck++) {
        __syncthreads();
#pragma unroll
        for (int j = 0; j < 4; j++) {
            int idx = tid + 256 * j;
            int r   = idx >> 3;
            int c   = (idx & 7) << 2;
            float4 av = *(const float4*)(A + (size_t)(bm + r) * K + ck * 32 + c);
            float4 wv = *(const float4*)(W + (size_t)(bn + r) * K + ck * 32 + c);

            int w0 = c >> 1, w1 = w0 + 1;
            int c0p = permcol(w0), c1p = permcol(w1);

            uint32_t wh, wl;
            split_pack2(av.x, av.y, wh, wl);
            Ah[r * GW_STRIDE + c0p] = wh;  Al[r * GW_STRIDE + c0p] = wl;
            split_pack2(av.z, av.w, wh, wl);
            Ah[r * GW_STRIDE + c1p] = wh;  Al[r * GW_STRIDE + c1p] = wl;
            split_pack2(wv.x, wv.y, wh, wl);
            Wh[r * GW_STRIDE + c0p] = wh;  Wl[r * GW_STRIDE + c0p] = wl;
            split_pack2(wv.z, wv.w, wh, wl);
            Wh[r * GW_STRIDE + c1p] = wh;  Wl[r * GW_STRIDE + c1p] = wl;
        }
        __syncthreads();

        uint2 bh0[4], bh1[4], bl0[4], bl1[4];
#pragma unroll
        for (int nt = 0; nt < 4; nt++) {
            int n = col0 + nt * 8 + gid;
            const uint2* ph = (const uint2*)(Wh + n * GW_STRIDE);
            const uint2* pl = (const uint2*)(Wl + n * GW_STRIDE);
            bh0[nt] = ph[tig];     bh1[nt] = ph[tig + 4];
            bl0[nt] = pl[tig];     bl1[nt] = pl[tig + 4];
        }

#pragma unroll
        for (int mt = 0; mt < 4; mt++) {
            int r1 = row0 + mt * 16 + gid;
            const uint2* ph1 = (const uint2*)(Ah + r1 * GW_STRIDE);
            const uint2* ph2 = (const uint2*)(Ah + (r1 + 8) * GW_STRIDE);
            const uint2* pl1 = (const uint2*)(Al + r1 * GW_STRIDE);
            const uint2* pl2 = (const uint2*)(Al + (r1 + 8) * GW_STRIDE);
            uint2 ah0 = ph1[tig], ah2 = ph1[tig + 4];
            uint2 ah1 = ph2[tig], ah3 = ph2[tig + 4];
            uint2 al0 = pl1[tig], al2 = pl1[tig + 4];
            uint2 al1 = pl2[tig], al3 = pl2[tig + 4];

#pragma unroll
            for (int nt = 0; nt < 4; nt++) {
                float* c = acc[mt][nt];
                mma_bf16(c[0],c[1],c[2],c[3], ah0.x,ah1.x,ah2.x,ah3.x, bh0[nt].x, bh1[nt].x);
                mma_bf16(c[0],c[1],c[2],c[3], al0.x,al1.x,al2.x,al3.x, bh0[nt].x, bh1[nt].x);
                mma_bf16(c[0],c[1],c[2],c[3], ah0.x,ah1.x,ah2.x,ah3.x, bl0[nt].x, bl1[nt].x);
                mma_bf16(c[0],c[1],c[2],c[3], ah0.y,ah1.y,ah2.y,ah3.y, bh0[nt].y, bh1[nt].y);
                mma_bf16(c[0],c[1],c[2],c[3], al0.y,al1.y,al2.y,al3.y, bh0[nt].y, bh1[nt].y);
                mma_bf16(c[0],c[1],c[2],c[3], ah0.y,ah1.y,ah2.y,ah3.y, bl0[nt].y, bl1[nt].y);
            }
        }
    }

#pragma unroll
    for (int mt = 0; mt < 4; mt++) {
        int row = bm + row0 + mt * 16 + gid;
#pragma unroll
        for (int nt = 0; nt < 4; nt++) {
            int col = bn + col0 + nt * 8 + 2 * tig;
            *(float2*)(C + (size_t)row * N + col)       = make_float2(acc[mt][nt][0], acc[mt][nt][1]);
            *(float2*)(C + (size_t)(row + 8) * N + col) = make_float2(acc[mt][nt][2], acc[mt][nt][3]);
        }
    }
}

// ---------------------------------------------------------------------------
// RoPE (pure fp32). In-place on Q and K.
// ---------------------------------------------------------------------------
__global__ void rope_kernel(float* __restrict__ Q, float* __restrict__ K,
                            const int* __restrict__ pos)
{
    const int total = B_ * S_ * D_ / 2;
    int idx = blockIdx.x * blockDim.x + threadIdx.x;
    if (idx >= total) return;

    const int i  = idx & (HD_ / 2 - 1);
    const int bs = idx >> 9;
    const int p  = pos[bs];

    float inv = exp2f(-(float)i * 0.41524101186092f);
    float ang = (float)p * inv;
    float c, s;
    sincosf(ang, &s, &c);

    const size_t base = (size_t)idx * 2;
    float q1 = Q[base], q2 = Q[base + 1];
    Q[base]     = q1 * c - q2 * s;
    Q[base + 1] = q1 * s + q2 * c;
    float k1 = K[base], k2 = K[base + 1];
    K[base]     = k1 * c - k2 * s;
    K[base + 1] = k1 * s + k2 * c;
}

// ---------------------------------------------------------------------------
// Tensor-core flash attention (bf16x3), causal.
// CTA: 64 q-rows, 4 warps (16 q-rows each), KV chunks of 64.
// Smem: Kh/Kl (2 chunks x 64 rows x 24 words, d-packed, permuted),
//       Vth/Vtl (transposed V: 2 kv-chunks x 64 d-rows x 26 words, kv-packed).
// ---------------------------------------------------------------------------
#define AT_KSTRIDE 24
#define AT_VSTRIDE 26
#define AT_KBUF (2 * 64 * AT_KSTRIDE)     // 3072 words
#define AT_VBUF (2 * 64 * AT_VSTRIDE)     // 3328 words
#define AT_SMEM_BYTES ((2 * AT_KBUF + 2 * AT_VBUF) * 4)   // 51200 B

__global__ __launch_bounds__(128) void attn_tc_kernel(
    const float* __restrict__ Q, const float* __restrict__ K,
    const float* __restrict__ V, float* __restrict__ O)
{
    extern __shared__ __align__(16) uint32_t smw[];
    uint32_t* Kh  = smw;
    uint32_t* Kl  = smw + AT_KBUF;
    uint32_t* Vth = smw + 2 * AT_KBUF;
    uint32_t* Vtl = smw + 2 * AT_KBUF + AT_VBUF;

    const int tid = threadIdx.x;
    const int wid = tid >> 5;
    const int lid = tid & 31;
    const int gid = lid >> 2;
    const int tig = lid & 3;
    const int bh  = blockIdx.y;
    const int b   = bh >> 4;
    const int h   = bh & 15;
    const int q0  = blockIdx.x * 64;

    const size_t boff = (size_t)b * S_ * D_ + (size_t)h * HD_;
    const float scale = 0.125f;

    // ---- Stage Q (scaled) into Kh/Kl, then read A-fragments to registers.
#pragma unroll
    for (int j = 0; j < 8; j++) {
        int idx = tid + 128 * j;           // 0..1023
        int r   = idx >> 4;                // q row 0..63
        int c   = (idx & 15) << 2;         // d col 0..60
        float4 qv = *(const float4*)(Q + boff + (size_t)(q0 + r) * D_ + c);
        qv.x *= scale; qv.y *= scale; qv.z *= scale; qv.w *= scale;
        int chunk = c >> 5, cc = c & 31;
        int base = (chunk * 64 + r) * AT_KSTRIDE;
        int c0p = permcol(cc >> 1), c1p = permcol((cc >> 1) + 1);
        uint32_t wh, wl;
        split_pack2(qv.x, qv.y, wh, wl);
        Kh[base + c0p] = wh;  Kl[base + c0p] = wl;
        split_pack2(qv.z, qv.w, wh, wl);
        Kh[base + c1p] = wh;  Kl[base + c1p] = wl;
    }
    __syncthreads();

    uint32_t qh[4][4], ql[4][4];   // [kstep][a-reg]
    {
        const int r1 = wid * 16 + gid;
#pragma unroll
        for (int chunk = 0; chunk < 2; chunk++) {
            const uint2* ph1 = (const uint2*)(Kh + (chunk * 64 + r1) * AT_KSTRIDE);
            const uint2* ph2 = (const uint2*)(Kh + (chunk * 64 + r1 + 8) * AT_KSTRIDE);
            const uint2* pl1 = (const uint2*)(Kl + (chunk * 64 + r1) * AT_KSTRIDE);
            const uint2* pl2 = (const uint2*)(Kl + (chunk * 64 + r1 + 8) * AT_KSTRIDE);
            uint2 x0 = ph1[tig], x2 = ph1[tig + 4];
            uint2 x1 = ph2[tig], x3 = ph2[tig + 4];
            qh[2*chunk][0] = x0.x; qh[2*chunk][1] = x1.x; qh[2*chunk][2] = x2.x; qh[2*chunk][3] = x3.x;
            qh[2*chunk+1][0] = x0.y; qh[2*chunk+1][1] = x1.y; qh[2*chunk+1][2] = x2.y; qh[2*chunk+1][3] = x3.y;
            uint2 y0 = pl1[tig], y2 = pl1[tig + 4];
            uint2 y1 = pl2[tig], y3 = pl2[tig + 4];
            ql[2*chunk][0] = y0.x; ql[2*chunk][1] = y1.x; ql[2*chunk][2] = y2.x; ql[2*chunk][3] = y3.x;
            ql[2*chunk+1][0] = y0.y; ql[2*chunk+1][1] = y1.y; ql[2*chunk+1][2] = y2.y; ql[2*chunk+1][3] = y3.y;
        }
    }
    __syncthreads();

    const int qg0 = q0 + wid * 16 + gid;
    const int qg1 = qg0 + 8;

    float m0 = -INFINITY, m1 = -INFINITY, l0 = 0.0f, l1 = 0.0f;
    float oa[8][4];
#pragma unroll
    for (int nt = 0; nt < 8; nt++)
#pragma unroll
        for (int e = 0; e < 4; e++) oa[nt][e] = 0.0f;

    for (int k0 = 0; k0 <= q0; k0 += 64) {
        // ---- Load K chunk (d-packed) and V chunk (transposed, kv-packed).
#pragma unroll
        for (int j = 0; j < 8; j++) {
            int idx = tid + 128 * j;
            int r   = idx >> 4;            // kv row 0..63
            int c   = (idx & 15) << 2;     // d col
            float4 kv = *(const float4*)(K + boff + (size_t)(k0 + r) * D_ + c);
            int chunk = c >> 5, cc = c & 31;
            int base = (chunk * 64 + r) * AT_KSTRIDE;
            int c0p = permcol(cc >> 1), c1p = permcol((cc >> 1) + 1);
            uint32_t wh, wl;
            split_pack2(kv.x, kv.y, wh, wl);
            Kh[base + c0p] = wh;  Kl[base + c0p] = wl;
            split_pack2(kv.z, kv.w, wh, wl);
            Kh[base + c1p] = wh;  Kl[base + c1p] = wl;

            float4 vv = *(const float4*)(V + boff + (size_t)(k0 + r) * D_ + c);
            // transpose into Vt: row = d, packed pairs along kv
            int vchunk = r >> 5;
            int w      = (r & 31) >> 1;
            int halfb  = r & 1;
            uint16_t* th = (uint16_t*)Vth;
            uint16_t* tl = (uint16_t*)Vtl;
            float vals[4] = {vv.x, vv.y, vv.z, vv.w};
#pragma unroll
            for (int i = 0; i < 4; i++) {
                __nv_bfloat16 hh, ll;
                split_bf16(vals[i], hh, ll);
                int word = (vchunk * 64 + (c + i)) * AT_VSTRIDE + permcol(w);
                th[word * 2 + halfb] = __bfloat16_as_ushort(hh);
                tl[word * 2 + halfb] = __bfloat16_as_ushort(ll);
            }
        }
        __syncthreads();

        // ---- S = Q K^T (bf16x3)
        float sc[8][4];
#pragma unroll
        for (int nt = 0; nt < 8; nt++)
#pragma unroll
            for (int e = 0; e < 4; e++) sc[nt][e] = 0.0f;

#pragma unroll
        for (int nt = 0; nt < 8; nt++) {
            int n = nt * 8 + gid;
            float* c = sc[nt];
#pragma unroll
            for (int chunk = 0; chunk < 2; chunk++) {
                const uint2* ph = (const uint2*)(Kh + (chunk * 64 + n) * AT_KSTRIDE);
                const uint2* pl = (const uint2*)(Kl + (chunk * 64 + n) * AT_KSTRIDE);
                uint2 bh0 = ph[tig], bh1 = ph[tig + 4];
                uint2 bl0 = pl[tig], bl1 = pl[tig + 4];
                int ks = 2 * chunk;
                mma_bf16(c[0],c[1],c[2],c[3], qh[ks][0],qh[ks][1],qh[ks][2],qh[ks][3], bh0.x, bh1.x);
                mma_bf16(c[0],c[1],c[2],c[3], ql[ks][0],ql[ks][1],ql[ks][2],ql[ks][3], bh0.x, bh1.x);
                mma_bf16(c[0],c[1],c[2],c[3], qh[ks][0],qh[ks][1],qh[ks][2],qh[ks][3], bl0.x, bl1.x);
                ks++;
                mma_bf16(c[0],c[1],c[2],c[3], qh[ks][0],qh[ks][1],qh[ks][2],qh[ks][3], bh0.y, bh1.y);
                mma_bf16(c[0],c[1],c[2],c[3], ql[ks][0],ql[ks][1],ql[ks][2],ql[ks][3], bh0.y, bh1.y);
                mma_bf16(c[0],c[1],c[2],c[3], qh[ks][0],qh[ks][1],qh[ks][2],qh[ks][3], bl0.y, bl1.y);
            }
        }

        // ---- Causal mask (diagonal chunk only) + online softmax
        const bool diag = (k0 == q0);
        float mx0 = -INFINITY, mx1 = -INFINITY;
#pragma unroll
        for (int nt = 0; nt < 8; nt++) {
            if (diag) {
                int kvb = k0 + nt * 8 + 2 * tig;
                if (kvb     > qg0) sc[nt][0] = -INFINITY;
                if (kvb + 1 > qg0) sc[nt][1] = -INFINITY;
                if (kvb     > qg1) sc[nt][2] = -INFINITY;
                if (kvb + 1 > qg1) sc[nt][3] = -INFINITY;
            }
            mx0 = fmaxf(mx0, fmaxf(sc[nt][0], sc[nt][1]));
            mx1 = fmaxf(mx1, fmaxf(sc[nt][2], sc[nt][3]));
        }
#pragma unroll
        for (int off = 1; off < 4; off <<= 1) {
            mx0 = fmaxf(mx0, __shfl_xor_sync(0xffffffffu, mx0, off));
            mx1 = fmaxf(mx1, __shfl_xor_sync(0xffffffffu, mx1, off));
        }
        float mn0 = fmaxf(m0, mx0), mn1 = fmaxf(m1, mx1);
        float cr0 = __expf(m0 - mn0), cr1 = __expf(m1 - mn1);
        float s0 = 0.0f, s1 = 0.0f;
#pragma unroll
        for (int nt = 0; nt < 8; nt++) {
            sc[nt][0] = __expf(sc[nt][0] - mn0);
            sc[nt][1] = __expf(sc[nt][1] - mn0);
            sc[nt][2] = __expf(sc[nt][2] - mn1);
            sc[nt][3] = __expf(sc[nt][3] - mn1);
            s0 += sc[nt][0] + sc[nt][1];
            s1 += sc[nt][2] + sc[nt][3];
        }
#pragma unroll
        for (int off = 1; off < 4; off <<= 1) {
            s0 += __shfl_xor_sync(0xffffffffu, s0, off);
            s1 += __shfl_xor_sync(0xffffffffu, s1, off);
        }
        l0 = l0 * cr0 + s0;   m0 = mn0;
        l1 = l1 * cr1 + s1;   m1 = mn1;
#pragma unroll
        for (int nt = 0; nt < 8; nt++) {
            oa[nt][0] *= cr0; oa[nt][1] *= cr0;
            oa[nt][2] *= cr1; oa[nt][3] *= cr1;
        }

        // ---- O += P V (bf16x3); P fragments built from sc registers.
#pragma unroll
        for (int ks = 0; ks < 4; ks++) {
            uint32_t pa_h[4], pa_l[4];
            split_pack2(sc[2*ks  ][0], sc[2*ks  ][1], pa_h[0], pa_l[0]);
            split_pack2(sc[2*ks  ][2], sc[2*ks  ][3], pa_h[1], pa_l[1]);
            split_pack2(sc[2*ks+1][0], sc[2*ks+1][1], pa_h[2], pa_l[2]);
            split_pack2(sc[2*ks+1][2], sc[2*ks+1][3], pa_h[3], pa_l[3]);

            const int vchunk = ks >> 1;
            const int half   = ks & 1;
#pragma unroll
            for (int nt = 0; nt < 8; nt++) {
                int n = nt * 8 + gid;       // d row of Vt
                const uint2* pv = (const uint2*)(Vth + (vchunk * 64 + n) * AT_VSTRIDE);
                const uint2* pw = (const uint2*)(Vtl + (vchunk * 64 + n) * AT_VSTRIDE);
                uint2 v0 = pv[tig], v1 = pv[tig + 4];
                uint2 w0 = pw[tig], w1 = pw[tig + 4];
                uint32_t bh0 = half ? v0.y : v0.x;
                uint32_t bh1 = half ? v1.y : v1.x;
                uint32_t bl0 = half ? w0.y : w0.x;
                uint32_t bl1 = half ? w1.y : w1.x;
                float* c = oa[nt];
                mma_bf16(c[0],c[1],c[2],c[3], pa_h[0],pa_h[1],pa_h[2],pa_h[3], bh0, bh1);
                mma_bf16(c[0],c[1],c[2],c[3], pa_l[0],pa_l[1],pa_l[2],pa_l[3], bh0, bh1);
                mma_bf16(c[0],c[1],c[2],c[3], pa_h[0],pa_h[1],pa_h[2],pa_h[3], bl0, bl1);
            }
        }
        __syncthreads();   // done with this chunk's smem before next load
    }

    // ---- Epilogue
    float inv0 = 1.0f / l0, inv1 = 1.0f / l1;
#pragma unroll
    for (int nt = 0; nt < 8; nt++) {
        int d = nt * 8 + 2 * tig;
        *(float2*)(O + boff + (size_t)qg0 * D_ + d) = make_float2(oa[nt][0] * inv0, oa[nt][1] * inv0);
        *(float2*)(O + boff + (size_t)qg1 * D_ + d) = make_float2(oa[nt][2] * inv1, oa[nt][3] * inv1);
    }
}

// ---------------------------------------------------------------------------
// Launch
// ---------------------------------------------------------------------------
extern "C" void kernel_launch(void* const* d_in, const int* in_sizes, int n_in,
                              void* d_out, int out_size)
{
    (void)in_sizes; (void)n_in; (void)out_size;
    const float* x   = (const float*)d_in[0];
    const int*   pos = (const int*)  d_in[1];
    const float* Wq  = (const float*)d_in[2];
    const float* Wk  = (const float*)d_in[3];
    const float* Wv  = (const float*)d_in[4];
    const float* Wo  = (const float*)d_in[5];
    float* out = (float*)d_out;

    void *pQ, *pK, *pV, *pO;
    cudaGetSymbolAddress(&pQ, g_Q);
    cudaGetSymbolAddress(&pK, g_K);
    cudaGetSymbolAddress(&pV, g_V);
    cudaGetSymbolAddress(&pO, g_O);

    const int M = B_ * S_;
    const int N = D_;
    const int K = D_;

    cudaFuncSetAttribute(gemm_bf16x3_kernel,
                         cudaFuncAttributeMaxDynamicSharedMemorySize, G3_SMEM_BYTES);
    cudaFuncSetAttribute(attn_tc_kernel,
                         cudaFuncAttributeMaxDynamicSharedMemorySize, AT_SMEM_BYTES);

    dim3 gblk(256);
    dim3 ggrid(N / 128, M / 128);

    gemm_bf16x3_kernel<<<ggrid, gblk, G3_SMEM_BYTES>>>(x, Wq, (float*)pQ, M, N, K);
    gemm_bf16x3_kernel<<<ggrid, gblk, G3_SMEM_BYTES>>>(x, Wk, (float*)pK, M, N, K);
    gemm_bf16x3_kernel<<<ggrid, gblk, G3_SMEM_BYTES>>>(x, Wv, (float*)pV, M, N, K);

    const int pairs = B_ * S_ * D_ / 2;
    rope_kernel<<<(pairs + 255) / 256, 256>>>((float*)pQ, (float*)pK, pos);

    dim3 agrid(S_ / 64, B_ * H_);
    attn_tc_kernel<<<agrid, 128, AT_SMEM_BYTES>>>((const float*)pQ, (const float*)pK,
                                                  (const float*)pV, (float*)pO);

    gemm_bf16x3_kernel<<<ggrid, gblk, G3_SMEM_BYTES>>>((const float*)pO, Wo, out, M, N, K);
}

// round 5
// speedup vs baseline: 2.1676x; 1.0285x over previous
#include <cuda_runtime.h>
#include <cuda_bf16.h>
#include <math.h>
#include <cstdint>

#define B_ 4
#define S_ 2048
#define D_ 1024
#define H_ 16
#define HD_ 64

// Scratch (device globals — no allocations allowed)
__device__ float g_Q[B_*S_*D_];
__device__ float g_K[B_*S_*D_];
__device__ float g_V[B_*S_*D_];
__device__ float g_O[B_*S_*D_];

// Pre-converted attention operands (packed bf16x2, permuted for MMA frags)
// Q/K: [b,h,s, 32 words]   (words = packed d-pairs, permuted per 16-word group)
// V:   [b,h,d, S/2 words]  (words = packed kv-pairs, permuted per 16-word group)
#define QKW (B_*H_*S_*32)
#define VW  (B_*H_*64*(S_/2))
__device__ uint32_t Qg_h[QKW];
__device__ uint32_t Qg_l[QKW];
__device__ uint32_t Kg_h[QKW];
__device__ uint32_t Kg_l[QKW];
__device__ uint32_t Vg_h[VW];
__device__ uint32_t Vg_l[VW];

// ---------------------------------------------------------------------------
// mma.sync helpers
// ---------------------------------------------------------------------------
__device__ __forceinline__ void mma_bf16(float& c0, float& c1, float& c2, float& c3,
                                         uint32_t a0, uint32_t a1, uint32_t a2, uint32_t a3,
                                         uint32_t b0, uint32_t b1)
{
    asm volatile(
        "mma.sync.aligned.m16n8k16.row.col.f32.bf16.bf16.f32 "
        "{%0,%1,%2,%3}, {%4,%5,%6,%7}, {%8,%9}, {%0,%1,%2,%3};"
        : "+f"(c0), "+f"(c1), "+f"(c2), "+f"(c3)
        : "r"(a0), "r"(a1), "r"(a2), "r"(a3), "r"(b0), "r"(b1));
}

__device__ __forceinline__ uint32_t pack_bf16(__nv_bfloat16 lo16, __nv_bfloat16 hi16) {
    return (uint32_t)__bfloat16_as_ushort(lo16)
         | ((uint32_t)__bfloat16_as_ushort(hi16) << 16);
}

__device__ __forceinline__ void split_bf16(float x, __nv_bfloat16& h, __nv_bfloat16& l) {
    h = __float2bfloat16_rn(x);
    l = __float2bfloat16_rn(x - __bfloat162float(h));
}

__device__ __forceinline__ void split_pack2(float x0, float x1, uint32_t& wh, uint32_t& wl) {
    __nv_bfloat16 h0, l0, h1, l1;
    split_bf16(x0, h0, l0);
    split_bf16(x1, h1, l1);
    wh = pack_bf16(h0, h1);
    wl = pack_bf16(l0, l1);
}

__device__ __forceinline__ int permcol(int w) { return 2 * (w & 7) + (w >> 3); }

// ---------------------------------------------------------------------------
// bf16x3 NT GEMM (unchanged — verified)
// ---------------------------------------------------------------------------
#define GW_STRIDE 24
#define GW_TILE   (128 * GW_STRIDE)
#define G3_SMEM_BYTES (4 * GW_TILE * 4)

__global__ __launch_bounds__(256) void gemm_bf16x3_kernel(
    const float* __restrict__ A, const float* __restrict__ W,
    float* __restrict__ C, int M, int N, int K)
{
    extern __shared__ __align__(16) uint32_t sm3[];
    uint32_t* Ah = sm3;
    uint32_t* Al = sm3 + GW_TILE;
    uint32_t* Wh = sm3 + 2 * GW_TILE;
    uint32_t* Wl = sm3 + 3 * GW_TILE;

    const int tid = threadIdx.x;
    const int wid = tid >> 5;
    const int lid = tid & 31;
    const int gid = lid >> 2;
    const int tig = lid & 3;
    const int row0 = (wid >> 2) * 64;
    const int col0 = (wid & 3) * 32;
    const int bm = blockIdx.y * 128;
    const int bn = blockIdx.x * 128;

    float acc[4][4][4];
#pragma unroll
    for (int mt = 0; mt < 4; mt++)
#pragma unroll
        for (int nt = 0; nt < 4; nt++)
#pragma unroll
            for (int e = 0; e < 4; e++) acc[mt][nt][e] = 0.0f;

    const int nchunk = K / 32;
    for (int ck = 0; ck < nchunk; ck++) {
        __syncthreads();
#pragma unroll
        for (int j = 0; j < 4; j++) {
            int idx = tid + 256 * j;
            int r   = idx >> 3;
            int c   = (idx & 7) << 2;
            float4 av = *(const float4*)(A + (size_t)(bm + r) * K + ck * 32 + c);
            float4 wv = *(const float4*)(W + (size_t)(bn + r) * K + ck * 32 + c);

            int w0 = c >> 1, w1 = w0 + 1;
            int c0p = permcol(w0), c1p = permcol(w1);

            uint32_t wh, wl;
            split_pack2(av.x, av.y, wh, wl);
            Ah[r * GW_STRIDE + c0p] = wh;  Al[r * GW_STRIDE + c0p] = wl;
            split_pack2(av.z, av.w, wh, wl);
            Ah[r * GW_STRIDE + c1p] = wh;  Al[r * GW_STRIDE + c1p] = wl;
            split_pack2(wv.x, wv.y, wh, wl);
            Wh[r * GW_STRIDE + c0p] = wh;  Wl[r * GW_STRIDE + c0p] = wl;
            split_pack2(wv.z, wv.w, wh, wl);
            Wh[r * GW_STRIDE + c1p] = wh;  Wl[r * GW_STRIDE + c1p] = wl;
        }
        __syncthreads();

        uint2 bh0[4], bh1[4], bl0[4], bl1[4];
#pragma unroll
        for (int nt = 0; nt < 4; nt++) {
            int n = col0 + nt * 8 + gid;
            const uint2* ph = (const uint2*)(Wh + n * GW_STRIDE);
            const uint2* pl = (const uint2*)(Wl + n * GW_STRIDE);
            bh0[nt] = ph[tig];     bh1[nt] = ph[tig + 4];
            bl0[nt] = pl[tig];     bl1[nt] = pl[tig + 4];
        }

#pragma unroll
        for (int mt = 0; mt < 4; mt++) {
            int r1 = row0 + mt * 16 + gid;
            const uint2* ph1 = (const uint2*)(Ah + r1 * GW_STRIDE);
            const uint2* ph2 = (const uint2*)(Ah + (r1 + 8) * GW_STRIDE);
            const uint2* pl1 = (const uint2*)(Al + r1 * GW_STRIDE);
            const uint2* pl2 = (const uint2*)(Al + (r1 + 8) * GW_STRIDE);
            uint2 ah0 = ph1[tig], ah2 = ph1[tig + 4];
            uint2 ah1 = ph2[tig], ah3 = ph2[tig + 4];
            uint2 al0 = pl1[tig], al2 = pl1[tig + 4];
            uint2 al1 = pl2[tig], al3 = pl2[tig + 4];

#pragma unroll
            for (int nt = 0; nt < 4; nt++) {
                float* c = acc[mt][nt];
                mma_bf16(c[0],c[1],c[2],c[3], ah0.x,ah1.x,ah2.x,ah3.x, bh0[nt].x, bh1[nt].x);
                mma_bf16(c[0],c[1],c[2],c[3], al0.x,al1.x,al2.x,al3.x, bh0[nt].x, bh1[nt].x);
                mma_bf16(c[0],c[1],c[2],c[3], ah0.x,ah1.x,ah2.x,ah3.x, bl0[nt].x, bl1[nt].x);
                mma_bf16(c[0],c[1],c[2],c[3], ah0.y,ah1.y,ah2.y,ah3.y, bh0[nt].y, bh1[nt].y);
                mma_bf16(c[0],c[1],c[2],c[3], al0.y,al1.y,al2.y,al3.y, bh0[nt].y, bh1[nt].y);
                mma_bf16(c[0],c[1],c[2],c[3], ah0.y,ah1.y,ah2.y,ah3.y, bl0[nt].y, bl1[nt].y);
            }
        }
    }

#pragma unroll
    for (int mt = 0; mt < 4; mt++) {
        int row = bm + row0 + mt * 16 + gid;
#pragma unroll
        for (int nt = 0; nt < 4; nt++) {
            int col = bn + col0 + nt * 8 + 2 * tig;
            *(float2*)(C + (size_t)row * N + col)       = make_float2(acc[mt][nt][0], acc[mt][nt][1]);
            *(float2*)(C + (size_t)(row + 8) * N + col) = make_float2(acc[mt][nt][2], acc[mt][nt][3]);
        }
    }
}

// ---------------------------------------------------------------------------
// Fused RoPE + bf16 split/pack/permute for Q (with 1/8 scale) and K.
// One thread per d-pair. Output layout: [b,h,s,32 words].
// ---------------------------------------------------------------------------
__global__ void qk_conv_kernel(const float* __restrict__ Q, const float* __restrict__ K,
                               const int* __restrict__ pos,
                               uint32_t* __restrict__ Qh, uint32_t* __restrict__ Ql,
                               uint32_t* __restrict__ Kh, uint32_t* __restrict__ Kl)
{
    int idx = blockIdx.x * blockDim.x + threadIdx.x;   // 0 .. B*S*H*32-1
    const int w  = idx & 31;           // d-pair in head
    const int h  = (idx >> 5) & 15;
    const int bs = idx >> 9;
    const int b  = bs >> 11;
    const int s  = bs & 2047;
    const int p  = pos[bs];

    float inv = exp2f(-(float)w * 0.41524101186092f);
    float ang = (float)p * inv;
    float c, sn;
    sincosf(ang, &sn, &c);

    const size_t src = (size_t)bs * D_ + h * HD_ + 2 * w;
    float2 qv = *(const float2*)(Q + src);
    float2 kv = *(const float2*)(K + src);

    float q1 = (qv.x * c - qv.y * sn) * 0.125f;
    float q2 = (qv.x * sn + qv.y * c) * 0.125f;
    float k1 = kv.x * c - kv.y * sn;
    float k2 = kv.x * sn + kv.y * c;

    const size_t dst = ((size_t)(b * H_ + h) * S_ + s) * 32
                     + (w >> 4) * 16 + permcol(w & 15);
    uint32_t wh, wl;
    split_pack2(q1, q2, wh, wl);
    Qh[dst] = wh;  Ql[dst] = wl;
    split_pack2(k1, k2, wh, wl);
    Kh[dst] = wh;  Kl[dst] = wl;
}

// ---------------------------------------------------------------------------
// V transpose + bf16 split/pack/permute. CTA = one (b,h,64-kv block).
// Output layout: [b,h,d, S/2 words] (packed kv-pairs, permuted per 16-group).
// ---------------------------------------------------------------------------
__global__ __launch_bounds__(128) void v_conv_kernel(
    const float* __restrict__ V,
    uint32_t* __restrict__ Vh, uint32_t* __restrict__ Vl)
{
    __shared__ float tile[64 * 65];
    const int tid = threadIdx.x;
    const int cta = blockIdx.x;
    const int s0  = (cta & 31) * 64;
    const int bhh = cta >> 5;          // b*16+h
    const int b   = bhh >> 4;
    const int h   = bhh & 15;

#pragma unroll
    for (int j = 0; j < 8; j++) {
        int idx = tid + 128 * j;       // 0..1023
        int sl  = idx >> 4;
        int d4  = (idx & 15) << 2;
        float4 v = *(const float4*)(V + ((size_t)(b * S_ + s0 + sl)) * D_ + h * HD_ + d4);
        tile[sl * 65 + d4 + 0] = v.x;
        tile[sl * 65 + d4 + 1] = v.y;
        tile[sl * 65 + d4 + 2] = v.z;
        tile[sl * 65 + d4 + 3] = v.w;
    }
    __syncthreads();

    const int d   = tid >> 1;
    const int grp = tid & 1;
    const size_t rowbase = ((size_t)bhh * 64 + d) * (S_ / 2) + (s0 >> 1) + grp * 16;
#pragma unroll
    for (int j = 0; j < 16; j++) {
        int kl = grp * 32 + 2 * j;
        float v0 = tile[kl * 65 + d];
        float v1 = tile[(kl + 1) * 65 + d];
        uint32_t wh, wl;
        split_pack2(v0, v1, wh, wl);
        size_t dst = rowbase + permcol(j);
        Vh[dst] = wh;  Vl[dst] = wl;
    }
}

// ---------------------------------------------------------------------------
// Tensor-core flash attention (bf16x3), causal. Operands pre-converted.
// CTA: 64 q-rows, 4 warps. Smem: Kh/Kl/Vh/Vl 64 rows x 36 words each.
// ---------------------------------------------------------------------------
#define AT_ST 36
#define AT_BUF (64 * AT_ST)                       // 2304 words
#define AT_SMEM_BYTES (4 * AT_BUF * 4)            // 36864 B

__global__ __launch_bounds__(128) void attn_tc_kernel(
    const uint32_t* __restrict__ Qh, const uint32_t* __restrict__ Ql,
    const uint32_t* __restrict__ Kgh, const uint32_t* __restrict__ Kgl,
    const uint32_t* __restrict__ Vgh, const uint32_t* __restrict__ Vgl,
    float* __restrict__ O)
{
    extern __shared__ __align__(16) uint32_t smw[];
    uint32_t* Kh = smw;
    uint32_t* Kl = smw + AT_BUF;
    uint32_t* Vh = smw + 2 * AT_BUF;
    uint32_t* Vl = smw + 3 * AT_BUF;

    const int tid = threadIdx.x;
    const int wid = tid >> 5;
    const int lid = tid & 31;
    const int gid = lid >> 2;
    const int tig = lid & 3;
    const int bh  = blockIdx.y;       // b*16+h
    const int q0  = blockIdx.x * 64;

    const size_t kqbase = (size_t)bh * S_ * 32;        // word base of Q/K rows
    const size_t vbase  = (size_t)bh * 64 * (S_ / 2);  // word base of V rows

    // ---- Stage Q rows into Kh/Kl, read A-fragments.
    {
        const uint4* srcH = (const uint4*)(Qh + kqbase + (size_t)q0 * 32);
        const uint4* srcL = (const uint4*)(Ql + kqbase + (size_t)q0 * 32);
#pragma unroll
        for (int j = 0; j < 4; j++) {
            int e  = tid + 128 * j;    // 0..511
            int r  = e >> 3;
            int q4 = e & 7;
            *(uint4*)(Kh + r * AT_ST + q4 * 4) = srcH[r * 8 + q4];
            *(uint4*)(Kl + r * AT_ST + q4 * 4) = srcL[r * 8 + q4];
        }
    }
    __syncthreads();

    uint32_t qh[4][4], ql[4][4];
    {
        const int r1 = wid * 16 + gid;
#pragma unroll
        for (int chunk = 0; chunk < 2; chunk++) {
            const uint2* ph1 = (const uint2*)(Kh + r1 * AT_ST + chunk * 16);
            const uint2* ph2 = (const uint2*)(Kh + (r1 + 8) * AT_ST + chunk * 16);
            const uint2* pl1 = (const uint2*)(Kl + r1 * AT_ST + chunk * 16);
            const uint2* pl2 = (const uint2*)(Kl + (r1 + 8) * AT_ST + chunk * 16);
            uint2 x0 = ph1[tig], x2 = ph1[tig + 4];
            uint2 x1 = ph2[tig], x3 = ph2[tig + 4];
            qh[2*chunk][0] = x0.x; qh[2*chunk][1] = x1.x; qh[2*chunk][2] = x2.x; qh[2*chunk][3] = x3.x;
            qh[2*chunk+1][0] = x0.y; qh[2*chunk+1][1] = x1.y; qh[2*chunk+1][2] = x2.y; qh[2*chunk+1][3] = x3.y;
            uint2 y0 = pl1[tig], y2 = pl1[tig + 4];
            uint2 y1 = pl2[tig], y3 = pl2[tig + 4];
            ql[2*chunk][0] = y0.x; ql[2*chunk][1] = y1.x; ql[2*chunk][2] = y2.x; ql[2*chunk][3] = y3.x;
            ql[2*chunk+1][0] = y0.y; ql[2*chunk+1][1] = y1.y; ql[2*chunk+1][2] = y2.y; ql[2*chunk+1][3] = y3.y;
        }
    }
    __syncthreads();

    const int qg0 = q0 + wid * 16 + gid;
    const int qg1 = qg0 + 8;

    float m0 = -INFINITY, m1 = -INFINITY, l0 = 0.0f, l1 = 0.0f;
    float oa[8][4];
#pragma unroll
    for (int nt = 0; nt < 8; nt++)
#pragma unroll
        for (int e = 0; e < 4; e++) oa[nt][e] = 0.0f;

    for (int k0 = 0; k0 <= q0; k0 += 64) {
        // ---- Pure block copy: K rows + V rows for this chunk.
        {
            const uint4* kH = (const uint4*)(Kgh + kqbase + (size_t)k0 * 32);
            const uint4* kL = (const uint4*)(Kgl + kqbase + (size_t)k0 * 32);
            const uint4* vH = (const uint4*)(Vgh + vbase);
            const uint4* vL = (const uint4*)(Vgl + vbase);
            const int voff = k0 >> 3;  // uint4 offset within V row (256 per row)
#pragma unroll
            for (int j = 0; j < 4; j++) {
                int e  = tid + 128 * j;
                int r  = e >> 3;
                int q4 = e & 7;
                *(uint4*)(Kh + r * AT_ST + q4 * 4) = kH[r * 8 + q4];
                *(uint4*)(Kl + r * AT_ST + q4 * 4) = kL[r * 8 + q4];
                *(uint4*)(Vh + r * AT_ST + q4 * 4) = vH[r * 256 + voff + q4];
                *(uint4*)(Vl + r * AT_ST + q4 * 4) = vL[r * 256 + voff + q4];
            }
        }
        __syncthreads();

        // ---- S = Q K^T (bf16x3)
        float sc[8][4];
#pragma unroll
        for (int nt = 0; nt < 8; nt++)
#pragma unroll
            for (int e = 0; e < 4; e++) sc[nt][e] = 0.0f;

#pragma unroll
        for (int nt = 0; nt < 8; nt++) {
            int n = nt * 8 + gid;
            float* c = sc[nt];
#pragma unroll
            for (int chunk = 0; chunk < 2; chunk++) {
                const uint2* ph = (const uint2*)(Kh + n * AT_ST + chunk * 16);
                const uint2* pl = (const uint2*)(Kl + n * AT_ST + chunk * 16);
                uint2 bh0 = ph[tig], bh1 = ph[tig + 4];
                uint2 bl0 = pl[tig], bl1 = pl[tig + 4];
                int ks = 2 * chunk;
                mma_bf16(c[0],c[1],c[2],c[3], qh[ks][0],qh[ks][1],qh[ks][2],qh[ks][3], bh0.x, bh1.x);
                mma_bf16(c[0],c[1],c[2],c[3], ql[ks][0],ql[ks][1],ql[ks][2],ql[ks][3], bh0.x, bh1.x);
                mma_bf16(c[0],c[1],c[2],c[3], qh[ks][0],qh[ks][1],qh[ks][2],qh[ks][3], bl0.x, bl1.x);
                ks++;
                mma_bf16(c[0],c[1],c[2],c[3], qh[ks][0],qh[ks][1],qh[ks][2],qh[ks][3], bh0.y, bh1.y);
                mma_bf16(c[0],c[1],c[2],c[3], ql[ks][0],ql[ks][1],ql[ks][2],ql[ks][3], bh0.y, bh1.y);
                mma_bf16(c[0],c[1],c[2],c[3], qh[ks][0],qh[ks][1],qh[ks][2],qh[ks][3], bl0.y, bl1.y);
            }
        }

        // ---- Causal mask + online softmax
        const bool diag = (k0 == q0);
        float mx0 = -INFINITY, mx1 = -INFINITY;
#pragma unroll
        for (int nt = 0; nt < 8; nt++) {
            if (diag) {
                int kvb = k0 + nt * 8 + 2 * tig;
                if (kvb     > qg0) sc[nt][0] = -INFINITY;
                if (kvb + 1 > qg0) sc[nt][1] = -INFINITY;
                if (kvb     > qg1) sc[nt][2] = -INFINITY;
                if (kvb + 1 > qg1) sc[nt][3] = -INFINITY;
            }
            mx0 = fmaxf(mx0, fmaxf(sc[nt][0], sc[nt][1]));
            mx1 = fmaxf(mx1, fmaxf(sc[nt][2], sc[nt][3]));
        }
#pragma unroll
        for (int off = 1; off < 4; off <<= 1) {
            mx0 = fmaxf(mx0, __shfl_xor_sync(0xffffffffu, mx0, off));
            mx1 = fmaxf(mx1, __shfl_xor_sync(0xffffffffu, mx1, off));
        }
        float mn0 = fmaxf(m0, mx0), mn1 = fmaxf(m1, mx1);
        float cr0 = __expf(m0 - mn0), cr1 = __expf(m1 - mn1);
        float s0 = 0.0f, s1 = 0.0f;
#pragma unroll
        for (int nt = 0; nt < 8; nt++) {
            sc[nt][0] = __expf(sc[nt][0] - mn0);
            sc[nt][1] = __expf(sc[nt][1] - mn0);
            sc[nt][2] = __expf(sc[nt][2] - mn1);
            sc[nt][3] = __expf(sc[nt][3] - mn1);
            s0 += sc[nt][0] + sc[nt][1];
            s1 += sc[nt][2] + sc[nt][3];
        }
#pragma unroll
        for (int off = 1; off < 4; off <<= 1) {
            s0 += __shfl_xor_sync(0xffffffffu, s0, off);
            s1 += __shfl_xor_sync(0xffffffffu, s1, off);
        }
        l0 = l0 * cr0 + s0;   m0 = mn0;
        l1 = l1 * cr1 + s1;   m1 = mn1;
#pragma unroll
        for (int nt = 0; nt < 8; nt++) {
            oa[nt][0] *= cr0; oa[nt][1] *= cr0;
            oa[nt][2] *= cr1; oa[nt][3] *= cr1;
        }

        // ---- O += P V (bf16x3)
#pragma unroll
        for (int ks = 0; ks < 4; ks++) {
            uint32_t pa_h[4], pa_l[4];
            split_pack2(sc[2*ks  ][0], sc[2*ks  ][1], pa_h[0], pa_l[0]);
            split_pack2(sc[2*ks  ][2], sc[2*ks  ][3], pa_h[1], pa_l[1]);
            split_pack2(sc[2*ks+1][0], sc[2*ks+1][1], pa_h[2], pa_l[2]);
            split_pack2(sc[2*ks+1][2], sc[2*ks+1][3], pa_h[3], pa_l[3]);

            const int vchunk = ks >> 1;
            const int half   = ks & 1;
#pragma unroll
            for (int nt = 0; nt < 8; nt++) {
                int n = nt * 8 + gid;
                const uint2* pv = (const uint2*)(Vh + n * AT_ST + vchunk * 16);
                const uint2* pw = (const uint2*)(Vl + n * AT_ST + vchunk * 16);
                uint2 v0 = pv[tig], v1 = pv[tig + 4];
                uint2 w0 = pw[tig], w1 = pw[tig + 4];
                uint32_t vb0 = half ? v0.y : v0.x;
                uint32_t vb1 = half ? v1.y : v1.x;
                uint32_t wb0 = half ? w0.y : w0.x;
                uint32_t wb1 = half ? w1.y : w1.x;
                float* c = oa[nt];
                mma_bf16(c[0],c[1],c[2],c[3], pa_h[0],pa_h[1],pa_h[2],pa_h[3], vb0, vb1);
                mma_bf16(c[0],c[1],c[2],c[3], pa_l[0],pa_l[1],pa_l[2],pa_l[3], vb0, vb1);
                mma_bf16(c[0],c[1],c[2],c[3], pa_h[0],pa_h[1],pa_h[2],pa_h[3], wb0, wb1);
            }
        }
        __syncthreads();
    }

    // ---- Epilogue: O is [b,s,h,d]
    const int b = bh >> 4, h = bh & 15;
    const size_t boff = (size_t)b * S_ * D_ + (size_t)h * HD_;
    float inv0 = 1.0f / l0, inv1 = 1.0f / l1;
#pragma unroll
    for (int nt = 0; nt < 8; nt++) {
        int d = nt * 8 + 2 * tig;
        *(float2*)(O + boff + (size_t)qg0 * D_ + d) = make_float2(oa[nt][0] * inv0, oa[nt][1] * inv0);
        *(float2*)(O + boff + (size_t)qg1 * D_ + d) = make_float2(oa[nt][2] * inv1, oa[nt][3] * inv1);
    }
}

// ---------------------------------------------------------------------------
// Launch
// ---------------------------------------------------------------------------
extern "C" void kernel_launch(void* const* d_in, const int* in_sizes, int n_in,
                              void* d_out, int out_size)
{
    (void)in_sizes; (void)n_in; (void)out_size;
    const float* x   = (const float*)d_in[0];
    const int*   pos = (const int*)  d_in[1];
    const float* Wq  = (const float*)d_in[2];
    const float* Wk  = (const float*)d_in[3];
    const float* Wv  = (const float*)d_in[4];
    const float* Wo  = (const float*)d_in[5];
    float* out = (float*)d_out;

    void *pQ, *pK, *pV, *pO;
    void *pQh, *pQl, *pKh, *pKl, *pVh, *pVl;
    cudaGetSymbolAddress(&pQ, g_Q);
    cudaGetSymbolAddress(&pK, g_K);
    cudaGetSymbolAddress(&pV, g_V);
    cudaGetSymbolAddress(&pO, g_O);
    cudaGetSymbolAddress(&pQh, Qg_h);
    cudaGetSymbolAddress(&pQl, Qg_l);
    cudaGetSymbolAddress(&pKh, Kg_h);
    cudaGetSymbolAddress(&pKl, Kg_l);
    cudaGetSymbolAddress(&pVh, Vg_h);
    cudaGetSymbolAddress(&pVl, Vg_l);

    const int M = B_ * S_;
    const int N = D_;
    const int K = D_;

    cudaFuncSetAttribute(gemm_bf16x3_kernel,
                         cudaFuncAttributeMaxDynamicSharedMemorySize, G3_SMEM_BYTES);
    cudaFuncSetAttribute(attn_tc_kernel,
                         cudaFuncAttributeMaxDynamicSharedMemorySize, AT_SMEM_BYTES);

    dim3 gblk(256);
    dim3 ggrid(N / 128, M / 128);

    gemm_bf16x3_kernel<<<ggrid, gblk, G3_SMEM_BYTES>>>(x, Wq, (float*)pQ, M, N, K);
    gemm_bf16x3_kernel<<<ggrid, gblk, G3_SMEM_BYTES>>>(x, Wk, (float*)pK, M, N, K);
    gemm_bf16x3_kernel<<<ggrid, gblk, G3_SMEM_BYTES>>>(x, Wv, (float*)pV, M, N, K);

    const int npairs = B_ * S_ * H_ * 32;
    qk_conv_kernel<<<npairs / 256, 256>>>((const float*)pQ, (const float*)pK, pos,
                                          (uint32_t*)pQh, (uint32_t*)pQl,
                                          (uint32_t*)pKh, (uint32_t*)pKl);
    v_conv_kernel<<<B_ * H_ * (S_ / 64), 128>>>((const float*)pV,
                                                (uint32_t*)pVh, (uint32_t*)pVl);

    dim3 agrid(S_ / 64, B_ * H_);
    attn_tc_kernel<<<agrid, 128, AT_SMEM_BYTES>>>(
        (const uint32_t*)pQh, (const uint32_t*)pQl,
        (const uint32_t*)pKh, (const uint32_t*)pKl,
        (const uint32_t*)pVh, (const uint32_t*)pVl, (float*)pO);

    gemm_bf16x3_kernel<<<ggrid, gblk, G3_SMEM_BYTES>>>((const float*)pO, Wo, out, M, N, K);
}